// round 15
// baseline (speedup 1.0000x reference)
#include <cuda_runtime.h>
#include <cuda_fp16.h>
#include <cfloat>

#define T_DIM 2048
#define R_DIM 256
#define BS_DIM 32
#define IDX(t) ((t) + ((t) >> 5))   // smem skew: 1 pad float per 32
#define CSK 2112                    // skewed column size: 2048 + 64

// 64 MB transposed CDF scratch in HALF (within-128t-segment cumsums): [array][bs][r][t]
__device__ __half g_cdf[2][BS_DIM][R_DIM][T_DIM];
// per-segment totals fp32 (segments of 128 t): [array][bs][r][seg16]
__device__ float g_segtot[2][BS_DIM][R_DIM][16];
// per-block minima from cdf_kernel (2048 blocks, fully overwritten each call)
__device__ float g_blockmin[2048];

// ---------------- Kernel A: transpose + SEGMENT-LOCAL cumsum (fp16 out) + min ----------------
// grid 2048: [array(2)][bs(32)][rtile(8)][tquarter(4)], 128 threads (4 warps).
// Warp = one 128-t segment; lane = r within 32-wide r tile.
__global__ void __launch_bounds__(128) cdf_kernel(const float* __restrict__ x,
                                                  const float* __restrict__ y,
                                                  float* __restrict__ out) {
    __shared__ float tile[4][32][33];
    __shared__ float wmin[4];

    const int bid = blockIdx.x;
    const int a    = bid >> 10;
    const int rem  = bid & 1023;
    const int bs   = rem >> 5;
    const int rem2 = rem & 31;
    const int r0   = (rem2 >> 2) * 32;
    const int tb   = (rem2 & 3) * 512;

    if (bid == 0 && threadIdx.x < 4) out[threadIdx.x] = 0.0f;

    const int lane = threadIdx.x & 31;   // r'
    const int seg  = threadIdx.x >> 5;   // warp id (0..3) -> 128-t segment

    const float* src = (a ? y : x) + (size_t)bs * T_DIM * R_DIM + r0 + lane;

    float run = 0.0f;                    // within-segment running sum (fp32)
    float mn = FLT_MAX;

    const int row = lane >> 2;   // 0..7
    const int c4  = lane & 3;    // 0..3 (8-t group)

    float (*t33)[33] = tile[seg];        // this warp's 32x33 slice

    #pragma unroll 1
    for (int ch = 0; ch < 4; ch++) {
        const int t0 = tb + seg * 128 + ch * 32;
        #pragma unroll
        for (int h = 0; h < 2; h++) {
            float v[16];
            #pragma unroll
            for (int i = 0; i < 16; i++)
                v[i] = src[(size_t)(t0 + h * 16 + i) * R_DIM];
            #pragma unroll
            for (int i = 0; i < 16; i++) {
                mn = fminf(mn, v[i]);
                run += v[i];
                t33[lane][h * 16 + i] = run;   // tile holds SEGMENT cumsum
            }
        }
        __syncwarp();
        // drain transposed as half2: conflict-free scalar LDS, STG.128 (8 halves)
        #pragma unroll
        for (int rb = 0; rb < 4; rb++) {
            int rr = rb * 8 + row;
            union { __half2 h[4]; uint4 u; } pk;
            #pragma unroll
            for (int k = 0; k < 4; k++)
                pk.h[k] = __floats2half2_rn(t33[rr][c4 * 8 + 2 * k],
                                            t33[rr][c4 * 8 + 2 * k + 1]);
            *(uint4*)&g_cdf[a][bs][r0 + rr][t0 + c4 * 8] = pk.u;
        }
        __syncwarp();
    }
    // run = per-lane cumsum over this 128-t segment
    g_segtot[a][bs][r0 + lane][(tb >> 7) + seg] = run;

    // block min reduce -> g_blockmin[bid]
    for (int o = 16; o; o >>= 1) mn = fminf(mn, __shfl_xor_sync(0xffffffffu, mn, o));
    if (lane == 0) wmin[seg] = mn;
    __syncthreads();
    if (threadIdx.x == 0) {
        float m = fminf(fminf(wmin[0], wmin[1]), fminf(wmin[2], wmin[3]));
        g_blockmin[bid] = m;
    }
}

// ---------------- Kernel B: stage normalized CDFs (half in) + merge-path W2 ----------------
// grid 8192: [bs(32)][r(256)], 128 threads, ONE problem per block (smem 17 KB -> occ up).
__global__ void __launch_bounds__(128) w2_kernel(float* __restrict__ out) {
    __shared__ float sm[2 * CSK + 32];   // +32 pad: final-iteration dead loads
    __shared__ float coffs[2][16];       // pre-scaled: off_seg * inv
    __shared__ float cinv[2];
    __shared__ float csinv[2];           // shift * inv
    __shared__ float redsm[4];
    __shared__ float warr[4];

    const int tid = threadIdx.x;
    const int bs  = blockIdx.x >> 8;
    const int r0  = blockIdx.x & 255;

    // ---- global min from g_blockmin (2048 entries, L2-resident) ----
    {
        float m = FLT_MAX;
        #pragma unroll
        for (int k = 0; k < 16; k++) m = fminf(m, g_blockmin[k * 128 + tid]);
        for (int o = 16; o; o >>= 1) m = fminf(m, __shfl_xor_sync(0xffffffffu, m, o));
        if ((tid & 31) == 0) redsm[tid >> 5] = m;
    }
    __syncthreads();
    float mnv = fminf(fminf(redsm[0], redsm[1]), fminf(redsm[2], redsm[3]));
    const float shift = (mnv < 0.0f) ? (-1.1f * mnv) : 0.0f;

    // per-column segment-offset prefix + normalization (pre-scaled by inv)
    if (tid < 2) {
        int c = tid;                      // 0=x, 1=y
        const float* st = g_segtot[c][bs][r0];
        float pref[16];
        float runp = 0.0f;
        #pragma unroll
        for (int s = 0; s < 16; s++) { pref[s] = runp; runp += st[s]; }
        float inv = 1.0f / (runp + 2048.0f * shift);
        cinv[c] = inv;
        csinv[c] = shift * inv;
        #pragma unroll
        for (int s = 0; s < 16; s++) coffs[c][s] = pref[s] * inv;
    }
    __syncthreads();

    // stage: LDG.128 = 8 halves, convert + FFMA normalize, scalar skewed smem stores
    {
        const int c = tid >> 6;           // 0=x, 1=y
        const int l64 = tid & 63;
        const uint4* srcc = (const uint4*)&g_cdf[c][bs][r0][0];
        float* dst = sm + c * CSK;
        const float inv = cinv[c];
        const float si  = csinv[c];
        const float si2 = si + si;
        const float si4 = si2 + si2;
        #pragma unroll
        for (int it = 0; it < 4; it++) {
            int g = it * 64 + l64;        // 8-half group index
            uint4 u = srcc[g];
            int t = g * 8;
            float base = fmaf((float)(t + 1), si, coffs[c][t >> 7]);
            float2 f0 = __half22float2(*reinterpret_cast<__half2*>(&u.x));
            float2 f1 = __half22float2(*reinterpret_cast<__half2*>(&u.y));
            float2 f2 = __half22float2(*reinterpret_cast<__half2*>(&u.z));
            float2 f3 = __half22float2(*reinterpret_cast<__half2*>(&u.w));
            dst[IDX(t + 0)] = fmaf(f0.x, inv, base);
            dst[IDX(t + 1)] = fmaf(f0.y, inv, base + si);
            dst[IDX(t + 2)] = fmaf(f1.x, inv, base + si2);
            dst[IDX(t + 3)] = fmaf(f1.y, inv, base + si2 + si);
            float base4 = base + si4;
            dst[IDX(t + 4)] = fmaf(f2.x, inv, base4);
            dst[IDX(t + 5)] = fmaf(f2.y, inv, base4 + si);
            dst[IDX(t + 6)] = fmaf(f3.x, inv, base4 + si2);
            dst[IDX(t + 7)] = fmaf(f3.y, inv, base4 + si2 + si);
        }
    }
    __syncthreads();

    // ---- merge-path: 128 threads, 32 merged endpoints each ----
    const int l = tid;
    const int k0 = l * 32;
    const float* A = sm;
    const float* B = sm + CSK;

    int lo = (k0 > T_DIM) ? (k0 - T_DIM) : 0;
    int hi = (k0 < T_DIM) ? k0 : T_DIM;
    while (lo < hi) {
        int mid = (lo + hi) >> 1;
        if (A[IDX(mid)] <= B[IDX(k0 - 1 - mid)]) lo = mid + 1;
        else hi = mid;
    }
    int i = lo;
    int j = k0 - lo;

    float prevA = i ? A[IDX(i - 1)] : 0.0f;
    float prevB = j ? B[IDX(j - 1)] : 0.0f;
    float prev0 = fmaxf(prevA, prevB);
    float aq = (i < T_DIM) ? A[IDX(i)] : FLT_MAX;
    float bq = (j < T_DIM) ? B[IDX(j)] : FLT_MAX;
    float acc = 0.0f;

    if ((tid & 64) == 0) {
        // LEAN (ranks <= 2047): Abel form + exact per-chunk boundary terms.
        float fd0 = (float)(i - j);
        float fd2 = fd0 + fd0;
        acc = -prev0 * (fd0 * fd0);
        float lastq = prev0;
        #pragma unroll 8
        for (int s = 0; s < 32; s++) {
            bool takeA = (aq <= bq);
            float q = fminf(aq, bq);
            float sd = takeA ? -1.0f : 1.0f;
            float w = fmaf(sd, fd2, -1.0f);
            acc = fmaf(q, w, acc);
            fd2 = fmaf(-2.0f, sd, fd2);
            lastq = q;
            if (takeA) { i++; aq = A[IDX(i)]; }
            else       { j++; bq = B[IDX(j)]; }
        }
        float fdN = fd2 * 0.5f;
        acc = fmaf(lastq, fdN * fdN, acc);
    } else {
        // CLAMPED (ranks >= 2048)
        float prev = prev0;
        #pragma unroll 8
        for (int s = 0; s < 32; s++) {
            bool takeA = (aq <= bq);
            float q = fminf(aq, bq);
            int ic = (i < 2047) ? i : 2047;
            int jc = (j < 2047) ? j : 2047;
            float diff = (float)(ic - jc);
            acc += (q - prev) * (diff * diff);
            prev = q;
            if (takeA) { i++; aq = (i < T_DIM) ? A[IDX(i)] : FLT_MAX; }
            else       { j++; bq = (j < T_DIM) ? B[IDX(j)] : FLT_MAX; }
        }
    }
    acc *= (1.0f / 2048.0f) * (1.0f / 2048.0f);

    for (int o = 16; o; o >>= 1) acc += __shfl_xor_sync(0xffffffffu, acc, o);
    if ((tid & 31) == 0) warr[tid >> 5] = acc;
    __syncthreads();
    if (tid == 0) {
        float s = warr[0] + warr[1] + warr[2] + warr[3];
        atomicAdd(&out[bs >> 3], s);
    }
}

extern "C" void kernel_launch(void* const* d_in, const int* in_sizes, int n_in,
                              void* d_out, int out_size) {
    const float* x = (const float*)d_in[0];
    const float* y = (const float*)d_in[1];
    float* out = (float*)d_out;

    cdf_kernel<<<2 * BS_DIM * 32, 128>>>(x, y, out);
    w2_kernel<<<BS_DIM * R_DIM, 128>>>(out);
}

// round 16
// speedup vs baseline: 1.0255x; 1.0255x over previous
#include <cuda_runtime.h>
#include <cuda_fp16.h>
#include <cfloat>

#define T_DIM 2048
#define R_DIM 256
#define BS_DIM 32
#define IDX(t) ((t) + ((t) >> 5))   // smem skew: 1 pad float per 32
#define CSK 2112                    // skewed column size: 2048 + 64

// 64 MB blocked fp16 CDF scratch: [array][bs][rtile8][tblk32][r32][t64]
// (within-128t-segment cumsums; 4KB micro-tiles -> full-line stores AND loads)
__device__ __half g_cdf[2][BS_DIM][8][32][32][64];
// per-segment totals fp32 (segments of 128 t): [array][bs][r][seg16]
__device__ float g_segtot[2][BS_DIM][R_DIM][16];
// per-block minima from cdf_kernel (2048 blocks, fully overwritten each call)
__device__ float g_blockmin[2048];

// ---------------- Kernel A: transpose + SEGMENT-LOCAL cumsum (fp16 out) + min ----------------
// grid 2048: [array(2)][bs(32)][rtile(8)][tquarter(4)], 128 threads (4 warps).
// Warp = one 128-t segment; lane = r within 32-wide r tile.
// Tile is __half2[32][33]: holds 64 t per row, drained as full 4KB blocks.
__global__ void __launch_bounds__(128) cdf_kernel(const float* __restrict__ x,
                                                  const float* __restrict__ y,
                                                  float* __restrict__ out) {
    __shared__ __half2 tile[4][32][33];
    __shared__ float wmin[4];

    const int bid = blockIdx.x;
    const int a    = bid >> 10;
    const int rem  = bid & 1023;
    const int bs   = rem >> 5;
    const int rem2 = rem & 31;
    const int rt   = rem2 >> 2;          // rtile 0..7
    const int r0   = rt * 32;
    const int tb   = (rem2 & 3) * 512;   // t-quarter base

    if (bid == 0 && threadIdx.x < 4) out[threadIdx.x] = 0.0f;

    const int lane = threadIdx.x & 31;   // r'
    const int seg  = threadIdx.x >> 5;   // warp id (0..3) -> 128-t segment

    const float* src = (a ? y : x) + (size_t)bs * T_DIM * R_DIM + r0 + lane;

    float run = 0.0f;                    // within-segment running sum (fp32)
    float mn = FLT_MAX;

    const int row4 = lane >> 3;  // 0..3 (row group in drain)
    const int kk   = lane & 7;   // 0..7 (16B chunk in drain)

    __half2 (*t33)[33] = tile[seg];      // this warp's 32x33 half2 slice

    #pragma unroll 1
    for (int ch = 0; ch < 4; ch++) {
        const int t0 = tb + seg * 128 + ch * 32;
        const int w0 = (ch & 1) * 16;    // half2-word base within 64-t row window
        #pragma unroll
        for (int h = 0; h < 2; h++) {
            float v[16];
            #pragma unroll
            for (int i = 0; i < 16; i++)
                v[i] = src[(size_t)(t0 + h * 16 + i) * R_DIM];
            #pragma unroll
            for (int i = 0; i < 16; i += 2) {
                mn = fminf(mn, fminf(v[i], v[i + 1]));
                float r1 = run + v[i];
                run = r1 + v[i + 1];
                t33[lane][w0 + h * 8 + (i >> 1)] = __floats2half2_rn(r1, run);
            }
        }
        if (ch & 1) {
            __syncwarp();
            // drain 64-t block: full 4KB micro-tile, 512B contiguous per pass
            const int tbidx = (t0 - 32) >> 6;    // t64-block index 0..31
            uint4* dstu = (uint4*)&g_cdf[a][bs][rt][tbidx][0][0];
            #pragma unroll
            for (int rb = 0; rb < 8; rb++) {
                int rr = rb * 4 + row4;
                union { __half2 h[4]; uint4 u; } pk;
                #pragma unroll
                for (int p = 0; p < 4; p++) pk.h[p] = t33[rr][kk * 4 + p];
                dstu[rr * 8 + kk] = pk.u;        // 32 lanes = 512B contiguous
            }
            __syncwarp();
        }
    }
    // run = per-lane cumsum over this 128-t segment
    g_segtot[a][bs][r0 + lane][(tb >> 7) + seg] = run;

    // block min reduce -> g_blockmin[bid]
    for (int o = 16; o; o >>= 1) mn = fminf(mn, __shfl_xor_sync(0xffffffffu, mn, o));
    if (lane == 0) wmin[seg] = mn;
    __syncthreads();
    if (threadIdx.x == 0) {
        float m = fminf(fminf(wmin[0], wmin[1]), fminf(wmin[2], wmin[3]));
        g_blockmin[bid] = m;
    }
}

// ---------------- Kernel B: stage normalized CDFs (blocked half in) + merge-path W2 ----------------
// grid 8192: [bs(32)][r(256)], 128 threads, one problem per block.
__global__ void __launch_bounds__(128) w2_kernel(float* __restrict__ out) {
    __shared__ float sm[2 * CSK + 32];   // +32 pad: final-iteration dead loads
    __shared__ float coffs[2][16];       // pre-scaled: off_seg * inv
    __shared__ float cinv[2];
    __shared__ float csinv[2];           // shift * inv
    __shared__ float redsm[4];
    __shared__ float warr[4];

    const int tid = threadIdx.x;
    const int bs  = blockIdx.x >> 8;
    const int r0  = blockIdx.x & 255;

    // ---- global min from g_blockmin (2048 entries, L2-resident) ----
    {
        float m = FLT_MAX;
        #pragma unroll
        for (int k = 0; k < 16; k++) m = fminf(m, g_blockmin[k * 128 + tid]);
        for (int o = 16; o; o >>= 1) m = fminf(m, __shfl_xor_sync(0xffffffffu, m, o));
        if ((tid & 31) == 0) redsm[tid >> 5] = m;
    }
    __syncthreads();
    float mnv = fminf(fminf(redsm[0], redsm[1]), fminf(redsm[2], redsm[3]));
    const float shift = (mnv < 0.0f) ? (-1.1f * mnv) : 0.0f;

    // per-column segment-offset prefix + normalization (pre-scaled by inv)
    if (tid < 2) {
        int c = tid;                      // 0=x, 1=y
        const float* st = g_segtot[c][bs][r0];
        float pref[16];
        float runp = 0.0f;
        #pragma unroll
        for (int s = 0; s < 16; s++) { pref[s] = runp; runp += st[s]; }
        float inv = 1.0f / (runp + 2048.0f * shift);
        cinv[c] = inv;
        csinv[c] = shift * inv;
        #pragma unroll
        for (int s = 0; s < 16; s++) coffs[c][s] = pref[s] * inv;
    }
    __syncthreads();

    // stage: blocked-layout LDG.128 (full lines), convert + FFMA normalize
    {
        const int c = tid >> 6;           // 0=x, 1=y
        const int l64 = tid & 63;
        const int rt = r0 >> 5, r32 = r0 & 31;
        const uint4* srcc = (const uint4*)&g_cdf[c][bs][rt][0][r32][0];
        float* dst = sm + c * CSK;
        const float inv = cinv[c];
        const float si  = csinv[c];
        const float si2 = si + si;
        const float si4 = si2 + si2;
        #pragma unroll
        for (int it = 0; it < 4; it++) {
            int g = it * 64 + l64;        // 8-half group index (t = 8g)
            uint4 u = srcc[(g >> 3) * 256 + (g & 7)];   // tb stride = 256 uint4
            int t = g * 8;
            float base = fmaf((float)(t + 1), si, coffs[c][t >> 7]);
            float2 f0 = __half22float2(*reinterpret_cast<__half2*>(&u.x));
            float2 f1 = __half22float2(*reinterpret_cast<__half2*>(&u.y));
            float2 f2 = __half22float2(*reinterpret_cast<__half2*>(&u.z));
            float2 f3 = __half22float2(*reinterpret_cast<__half2*>(&u.w));
            dst[IDX(t + 0)] = fmaf(f0.x, inv, base);
            dst[IDX(t + 1)] = fmaf(f0.y, inv, base + si);
            dst[IDX(t + 2)] = fmaf(f1.x, inv, base + si2);
            dst[IDX(t + 3)] = fmaf(f1.y, inv, base + si2 + si);
            float base4 = base + si4;
            dst[IDX(t + 4)] = fmaf(f2.x, inv, base4);
            dst[IDX(t + 5)] = fmaf(f2.y, inv, base4 + si);
            dst[IDX(t + 6)] = fmaf(f3.x, inv, base4 + si2);
            dst[IDX(t + 7)] = fmaf(f3.y, inv, base4 + si2 + si);
        }
    }
    __syncthreads();

    // ---- merge-path: 128 threads, 32 merged endpoints each ----
    const int l = tid;
    const int k0 = l * 32;
    const float* A = sm;
    const float* B = sm + CSK;

    int lo = (k0 > T_DIM) ? (k0 - T_DIM) : 0;
    int hi = (k0 < T_DIM) ? k0 : T_DIM;
    while (lo < hi) {
        int mid = (lo + hi) >> 1;
        if (A[IDX(mid)] <= B[IDX(k0 - 1 - mid)]) lo = mid + 1;
        else hi = mid;
    }
    int i = lo;
    int j = k0 - lo;

    float prevA = i ? A[IDX(i - 1)] : 0.0f;
    float prevB = j ? B[IDX(j - 1)] : 0.0f;
    float prev0 = fmaxf(prevA, prevB);
    float aq = (i < T_DIM) ? A[IDX(i)] : FLT_MAX;
    float bq = (j < T_DIM) ? B[IDX(j)] : FLT_MAX;
    float acc = 0.0f;

    if ((tid & 64) == 0) {
        // LEAN (ranks <= 2047): Abel form + exact per-chunk boundary terms.
        float fd0 = (float)(i - j);
        float fd2 = fd0 + fd0;
        acc = -prev0 * (fd0 * fd0);
        float lastq = prev0;
        #pragma unroll 8
        for (int s = 0; s < 32; s++) {
            bool takeA = (aq <= bq);
            float q = fminf(aq, bq);
            float sd = takeA ? -1.0f : 1.0f;
            float w = fmaf(sd, fd2, -1.0f);
            acc = fmaf(q, w, acc);
            fd2 = fmaf(-2.0f, sd, fd2);
            lastq = q;
            if (takeA) { i++; aq = A[IDX(i)]; }
            else       { j++; bq = B[IDX(j)]; }
        }
        float fdN = fd2 * 0.5f;
        acc = fmaf(lastq, fdN * fdN, acc);
    } else {
        // CLAMPED (ranks >= 2048)
        float prev = prev0;
        #pragma unroll 8
        for (int s = 0; s < 32; s++) {
            bool takeA = (aq <= bq);
            float q = fminf(aq, bq);
            int ic = (i < 2047) ? i : 2047;
            int jc = (j < 2047) ? j : 2047;
            float diff = (float)(ic - jc);
            acc += (q - prev) * (diff * diff);
            prev = q;
            if (takeA) { i++; aq = (i < T_DIM) ? A[IDX(i)] : FLT_MAX; }
            else       { j++; bq = (j < T_DIM) ? B[IDX(j)] : FLT_MAX; }
        }
    }
    acc *= (1.0f / 2048.0f) * (1.0f / 2048.0f);

    for (int o = 16; o; o >>= 1) acc += __shfl_xor_sync(0xffffffffu, acc, o);
    if ((tid & 31) == 0) warr[tid >> 5] = acc;
    __syncthreads();
    if (tid == 0) {
        float s = warr[0] + warr[1] + warr[2] + warr[3];
        atomicAdd(&out[bs >> 3], s);
    }
}

extern "C" void kernel_launch(void* const* d_in, const int* in_sizes, int n_in,
                              void* d_out, int out_size) {
    const float* x = (const float*)d_in[0];
    const float* y = (const float*)d_in[1];
    float* out = (float*)d_out;

    cdf_kernel<<<2 * BS_DIM * 32, 128>>>(x, y, out);
    w2_kernel<<<BS_DIM * R_DIM, 128>>>(out);
}

// round 17
// speedup vs baseline: 1.0409x; 1.0150x over previous
#include <cuda_runtime.h>
#include <cuda_fp16.h>
#include <cfloat>

#define T_DIM 2048
#define R_DIM 256
#define BS_DIM 32
#define IDX(t) ((t) + ((t) >> 5))   // smem skew: 1 pad float per 32
#define CSK 2112                    // skewed column size: 2048 + 64

// 64 MB blocked fp16 CDF scratch: [array][bs][rtile8][tblk32][r32][t64]
// (within-128t-segment cumsums; 4KB micro-tiles -> full-line stores AND loads)
__device__ __half g_cdf[2][BS_DIM][8][32][32][64];
// per-segment totals fp32 (segments of 128 t): [array][bs][r][seg16]
__device__ float g_segtot[2][BS_DIM][R_DIM][16];
// per-block minima from cdf_kernel (2048 blocks, fully overwritten each call)
__device__ float g_blockmin[2048];

// ---------------- Kernel A: transpose + SEGMENT-LOCAL cumsum (fp16 out) + min ----------------
// grid 2048: [array(2)][bs(32)][rtile(8)][tquarter(4)], 128 threads (4 warps).
__global__ void __launch_bounds__(128) cdf_kernel(const float* __restrict__ x,
                                                  const float* __restrict__ y,
                                                  float* __restrict__ out) {
    __shared__ __half2 tile[4][32][33];
    __shared__ float wmin[4];

    const int bid = blockIdx.x;
    const int a    = bid >> 10;
    const int rem  = bid & 1023;
    const int bs   = rem >> 5;
    const int rem2 = rem & 31;
    const int rt   = rem2 >> 2;          // rtile 0..7
    const int r0   = rt * 32;
    const int tb   = (rem2 & 3) * 512;   // t-quarter base

    if (bid == 0 && threadIdx.x < 4) out[threadIdx.x] = 0.0f;

    const int lane = threadIdx.x & 31;   // r'
    const int seg  = threadIdx.x >> 5;   // warp id (0..3) -> 128-t segment

    const float* src = (a ? y : x) + (size_t)bs * T_DIM * R_DIM + r0 + lane;

    float run = 0.0f;                    // within-segment running sum (fp32)
    float mn = FLT_MAX;

    const int row4 = lane >> 3;  // 0..3 (row group in drain)
    const int kk   = lane & 7;   // 0..7 (16B chunk in drain)

    __half2 (*t33)[33] = tile[seg];      // this warp's 32x33 half2 slice

    #pragma unroll 1
    for (int ch = 0; ch < 4; ch++) {
        const int t0 = tb + seg * 128 + ch * 32;
        const int w0 = (ch & 1) * 16;    // half2-word base within 64-t row window
        #pragma unroll
        for (int h = 0; h < 2; h++) {
            float v[16];
            #pragma unroll
            for (int i = 0; i < 16; i++)
                v[i] = src[(size_t)(t0 + h * 16 + i) * R_DIM];
            #pragma unroll
            for (int i = 0; i < 16; i += 2) {
                mn = fminf(mn, fminf(v[i], v[i + 1]));
                float r1 = run + v[i];
                run = r1 + v[i + 1];
                t33[lane][w0 + h * 8 + (i >> 1)] = __floats2half2_rn(r1, run);
            }
        }
        if (ch & 1) {
            __syncwarp();
            // drain 64-t block: full 4KB micro-tile, 512B contiguous per pass
            const int tbidx = (t0 - 32) >> 6;    // t64-block index 0..31
            uint4* dstu = (uint4*)&g_cdf[a][bs][rt][tbidx][0][0];
            #pragma unroll
            for (int rb = 0; rb < 8; rb++) {
                int rr = rb * 4 + row4;
                union { __half2 h[4]; uint4 u; } pk;
                #pragma unroll
                for (int p = 0; p < 4; p++) pk.h[p] = t33[rr][kk * 4 + p];
                dstu[rr * 8 + kk] = pk.u;        // 32 lanes = 512B contiguous
            }
            __syncwarp();
        }
    }
    // run = per-lane cumsum over this 128-t segment
    g_segtot[a][bs][r0 + lane][(tb >> 7) + seg] = run;

    // block min reduce -> g_blockmin[bid]
    for (int o = 16; o; o >>= 1) mn = fminf(mn, __shfl_xor_sync(0xffffffffu, mn, o));
    if (lane == 0) wmin[seg] = mn;
    __syncthreads();
    if (threadIdx.x == 0) {
        float m = fminf(fminf(wmin[0], wmin[1]), fminf(wmin[2], wmin[3]));
        g_blockmin[bid] = m;
    }
}

// ---------------- Kernel B: stage normalized CDFs (blocked half in) + merge-path W2 ----------------
// grid 8192: [bs(32)][r(256)], 128 threads, one problem per block.
__global__ void __launch_bounds__(128) w2_kernel(float* __restrict__ out) {
    __shared__ float sm[2 * CSK + 32];   // +32 pad: final-iteration dead loads
    __shared__ float coffs[2][16];       // pre-scaled: off_seg * inv
    __shared__ float cinv[2];
    __shared__ float csinv[2];           // shift * inv
    __shared__ float redsm[4];
    __shared__ float warr[4];

    const int tid = threadIdx.x;
    const int bs  = blockIdx.x >> 8;
    const int r0  = blockIdx.x & 255;

    // ---- global min from g_blockmin (2048 entries, L2-resident, float4 loads) ----
    {
        const float4* bm = (const float4*)g_blockmin;   // 512 float4
        float m = FLT_MAX;
        #pragma unroll
        for (int k = 0; k < 4; k++) {
            float4 v = bm[k * 128 + tid];
            m = fminf(m, fminf(fminf(v.x, v.y), fminf(v.z, v.w)));
        }
        for (int o = 16; o; o >>= 1) m = fminf(m, __shfl_xor_sync(0xffffffffu, m, o));
        if ((tid & 31) == 0) redsm[tid >> 5] = m;
    }
    __syncthreads();
    float mnv = fminf(fminf(redsm[0], redsm[1]), fminf(redsm[2], redsm[3]));
    const float shift = (mnv < 0.0f) ? (-1.1f * mnv) : 0.0f;

    // per-column segment-offset prefix + normalization (pre-scaled by inv)
    if (tid < 2) {
        int c = tid;                      // 0=x, 1=y
        const float* st = g_segtot[c][bs][r0];
        float pref[16];
        float runp = 0.0f;
        #pragma unroll
        for (int s = 0; s < 16; s++) { pref[s] = runp; runp += st[s]; }
        float inv = 1.0f / (runp + 2048.0f * shift);
        cinv[c] = inv;
        csinv[c] = shift * inv;
        #pragma unroll
        for (int s = 0; s < 16; s++) coffs[c][s] = pref[s] * inv;
    }
    __syncthreads();

    // stage: blocked-layout LDG.128 (full lines), convert + FFMA normalize
    {
        const int c = tid >> 6;           // 0=x, 1=y
        const int l64 = tid & 63;
        const int rt = r0 >> 5, r32 = r0 & 31;
        const uint4* srcc = (const uint4*)&g_cdf[c][bs][rt][0][r32][0];
        float* dst = sm + c * CSK;
        const float inv = cinv[c];
        const float si  = csinv[c];
        const float si2 = si + si;
        const float si4 = si2 + si2;
        #pragma unroll
        for (int it = 0; it < 4; it++) {
            int g = it * 64 + l64;        // 8-half group index (t = 8g)
            uint4 u = srcc[(g >> 3) * 256 + (g & 7)];   // tb stride = 256 uint4
            int t = g * 8;
            float base = fmaf((float)(t + 1), si, coffs[c][t >> 7]);
            float2 f0 = __half22float2(*reinterpret_cast<__half2*>(&u.x));
            float2 f1 = __half22float2(*reinterpret_cast<__half2*>(&u.y));
            float2 f2 = __half22float2(*reinterpret_cast<__half2*>(&u.z));
            float2 f3 = __half22float2(*reinterpret_cast<__half2*>(&u.w));
            dst[IDX(t + 0)] = fmaf(f0.x, inv, base);
            dst[IDX(t + 1)] = fmaf(f0.y, inv, base + si);
            dst[IDX(t + 2)] = fmaf(f1.x, inv, base + si2);
            dst[IDX(t + 3)] = fmaf(f1.y, inv, base + si2 + si);
            float base4 = base + si4;
            dst[IDX(t + 4)] = fmaf(f2.x, inv, base4);
            dst[IDX(t + 5)] = fmaf(f2.y, inv, base4 + si);
            dst[IDX(t + 6)] = fmaf(f3.x, inv, base4 + si2);
            dst[IDX(t + 7)] = fmaf(f3.y, inv, base4 + si2 + si);
        }
    }
    __syncthreads();

    // ---- merge-path: 128 threads, 32 merged endpoints each ----
    const int l = tid;
    const int k0 = l * 32;
    const float* A = sm;
    const float* B = sm + CSK;

    int lo = (k0 > T_DIM) ? (k0 - T_DIM) : 0;
    int hi = (k0 < T_DIM) ? k0 : T_DIM;
    while (lo < hi) {
        int mid = (lo + hi) >> 1;
        if (A[IDX(mid)] <= B[IDX(k0 - 1 - mid)]) lo = mid + 1;
        else hi = mid;
    }
    int i = lo;
    int j = k0 - lo;

    float prevA = i ? A[IDX(i - 1)] : 0.0f;
    float prevB = j ? B[IDX(j - 1)] : 0.0f;
    float prev0 = fmaxf(prevA, prevB);
    float aq = (i < T_DIM) ? A[IDX(i)] : FLT_MAX;
    float bq = (j < T_DIM) ? B[IDX(j)] : FLT_MAX;
    float acc = 0.0f;

    // warp-uniform runtime selection: lean iff no lane in this warp can touch
    // index > 2047 during its 32-step chunk (i <= 2015 && j <= 2015 at entry).
    // Lane k0=4064 always has i0 >= 2016 -> warp 3 stays uniformly clamped.
    bool lean = __all_sync(0xffffffffu, (i <= 2015) && (j <= 2015));

    if (lean) {
        // LEAN: Abel form + exact per-chunk boundary terms; no clamps/guards.
        float fd0 = (float)(i - j);
        float fd2 = fd0 + fd0;
        acc = -prev0 * (fd0 * fd0);
        float lastq = prev0;
        #pragma unroll 8
        for (int s = 0; s < 32; s++) {
            bool takeA = (aq <= bq);
            float q = fminf(aq, bq);
            float sd = takeA ? -1.0f : 1.0f;
            float w = fmaf(sd, fd2, -1.0f);
            acc = fmaf(q, w, acc);
            fd2 = fmaf(-2.0f, sd, fd2);
            lastq = q;
            if (takeA) { i++; aq = A[IDX(i)]; }
            else       { j++; bq = B[IDX(j)]; }
        }
        float fdN = fd2 * 0.5f;
        acc = fmaf(lastq, fdN * fdN, acc);
    } else {
        // CLAMPED: explicit prev-form with index clamps.
        float prev = prev0;
        #pragma unroll 8
        for (int s = 0; s < 32; s++) {
            bool takeA = (aq <= bq);
            float q = fminf(aq, bq);
            int ic = (i < 2047) ? i : 2047;
            int jc = (j < 2047) ? j : 2047;
            float diff = (float)(ic - jc);
            acc += (q - prev) * (diff * diff);
            prev = q;
            if (takeA) { i++; aq = (i < T_DIM) ? A[IDX(i)] : FLT_MAX; }
            else       { j++; bq = (j < T_DIM) ? B[IDX(j)] : FLT_MAX; }
        }
    }
    acc *= (1.0f / 2048.0f) * (1.0f / 2048.0f);

    for (int o = 16; o; o >>= 1) acc += __shfl_xor_sync(0xffffffffu, acc, o);
    if ((tid & 31) == 0) warr[tid >> 5] = acc;
    __syncthreads();
    if (tid == 0) {
        float s = warr[0] + warr[1] + warr[2] + warr[3];
        atomicAdd(&out[bs >> 3], s);
    }
}

extern "C" void kernel_launch(void* const* d_in, const int* in_sizes, int n_in,
                              void* d_out, int out_size) {
    const float* x = (const float*)d_in[0];
    const float* y = (const float*)d_in[1];
    float* out = (float*)d_out;

    cdf_kernel<<<2 * BS_DIM * 32, 128>>>(x, y, out);
    w2_kernel<<<BS_DIM * R_DIM, 128>>>(out);
}